// round 15
// baseline (speedup 1.0000x reference)
#include <cuda_runtime.h>
#include <cuda_fp16.h>
#include <math.h>
#include <stdint.h>

// ---------------------------------------------------------------------------
// ViTBlockQuantum via mma.sync (HMMA) tensor cores. VQC collapsed analytically.
// GEMM1: scores[128x512] = Q[128x8] x Khead[8x512]  (m16n8k8, head-masked K)
// exp on MUFU f32 (R13 path), P stays in registers as GEMM2 A-fragments.
// GEMM2: [ctx|den][128x8] = P x W  (m16n8k16) -- W is per-head 8 cols
//        ({v0..v3,1,0,0,0} on h0 rows, {v4..v7,1,0,0,0} on h1 rows), so each
//        warp emits exactly its head's 4 ctx dims + denominator: half of
//        R13's GEMM2 work eliminated.
// ---------------------------------------------------------------------------

#define EGS 8
#define SSEQ 256
#define QH 128
#define QSCALE 0.72134752044448170368f   // 0.5 * log2(e)

// dynamic smem offsets (bytes)
#define QS   0        // Q fp16 [128 x 8]                   2048 B
#define KH   2048     // K fp16 head-masked [512 cols x 8]  8192 B
#define WD   10240    // W fp16 [8 ctx-cols x 520 k]        8320 B
#define RED  18560    // partial ctx f32 [4][128][6]        12288 B
#define SMEM_REQ 30848

static __device__ __forceinline__ float ex2f(float x) {
    float y; asm("ex2.approx.ftz.f32 %0, %1;" : "=f"(y) : "f"(x)); return y;
}
static __device__ __forceinline__ uint32_t pkh2(float hi, float lo) {
    uint32_t u; asm("cvt.rn.f16x2.f32 %0, %1, %2;" : "=r"(u) : "f"(hi), "f"(lo));
    return u;
}
static __device__ __forceinline__ uint32_t lds32(uint32_t a) {
    uint32_t v; asm volatile("ld.shared.b32 %0, [%1];" : "=r"(v) : "r"(a));
    return v;
}
static __device__ __forceinline__ void sts128(uint32_t a, uint32_t r0, uint32_t r1,
                                              uint32_t r2, uint32_t r3) {
    asm volatile("st.shared.v4.b32 [%0], {%1, %2, %3, %4};"
                 :: "r"(a), "r"(r0), "r"(r1), "r"(r2), "r"(r3) : "memory");
}
static __device__ __forceinline__ void sts16(uint32_t a, unsigned short v) {
    asm volatile("st.shared.u16 [%0], %1;" :: "r"(a), "h"(v) : "memory");
}

// D = A(16x8) * B(8x8) row.col, f32 accum from zero
static __device__ __forceinline__ void mma1688(float* d, uint32_t a0, uint32_t a1,
                                               uint32_t b0) {
    asm volatile(
        "mma.sync.aligned.m16n8k8.row.col.f32.f16.f16.f32 "
        "{%0,%1,%2,%3}, {%4,%5}, {%6}, {%7,%8,%9,%10};"
        : "=f"(d[0]), "=f"(d[1]), "=f"(d[2]), "=f"(d[3])
        : "r"(a0), "r"(a1), "r"(b0),
          "f"(0.f), "f"(0.f), "f"(0.f), "f"(0.f));
}
// D += A(16x16) * B(16x8) row.col, accumulate in place
static __device__ __forceinline__ void mma16816(float* d, const uint32_t* a,
                                                uint32_t b0, uint32_t b1) {
    asm volatile(
        "mma.sync.aligned.m16n8k16.row.col.f32.f16.f16.f32 "
        "{%0,%1,%2,%3}, {%4,%5,%6,%7}, {%8,%9}, {%0,%1,%2,%3};"
        : "+f"(d[0]), "+f"(d[1]), "+f"(d[2]), "+f"(d[3])
        : "r"(a[0]), "r"(a[1]), "r"(a[2]), "r"(a[3]), "r"(b0), "r"(b1));
}

static __device__ __forceinline__ void vqc8(const float a[8], float z[8]) {
    float c[8];
#pragma unroll
    for (int w = 0; w < 8; w++) c[w] = __cosf(a[w]);
    float p = c[0];
#pragma unroll
    for (int k = 1; k < 8; k++) { p *= c[k]; z[k] = p; }
    float q = c[1];
#pragma unroll
    for (int w = 2; w < 8; w++) q *= c[w];
    z[0] = q;
}

__global__ void __launch_bounds__(1024, 1) fused_mma_kernel(
    const float* __restrict__ x,
    const float* __restrict__ Wq, const float* __restrict__ Wk,
    const float* __restrict__ Wv, const float* __restrict__ Wc,
    const float* __restrict__ Wf,
    const float* __restrict__ w1, const float* __restrict__ b1,
    const float* __restrict__ w2, const float* __restrict__ b2,
    const float* __restrict__ g1, const float* __restrict__ be1,
    const float* __restrict__ g2, const float* __restrict__ be2,
    float* __restrict__ out)
{
    extern __shared__ __align__(16) char dynsm[];
    const uint32_t sb = (uint32_t)__cvta_generic_to_shared(dynsm);
    float* redf = (float*)(dynsm + RED);

    const int b    = blockIdx.x >> 1;
    const int qh   = blockIdx.x & 1;
    const int tid  = threadIdx.x;
    const int wid  = tid >> 5;
    const int lane = tid & 31;

    // ---------------- phase 1: stage Q / masked-K / W tiles (fp16) ----------
    if (tid < 256) {                        // K for token t -> 2 masked cols
        const int t = tid;
        const float4* xt = (const float4*)(x + (size_t)(b * SSEQ + t) * EGS);
        float4 x0 = xt[0], x1 = xt[1];
        float a[8], z[8];
        a[0] = x0.x + __ldg(Wk + 0); a[1] = x0.y + __ldg(Wk + 1);
        a[2] = x0.z + __ldg(Wk + 2); a[3] = x0.w + __ldg(Wk + 3);
        a[4] = x1.x + __ldg(Wk + 4); a[5] = x1.y + __ldg(Wk + 5);
        a[6] = x1.z + __ldg(Wk + 6); a[7] = x1.w + __ldg(Wk + 7);
        vqc8(a, z);
        // col t (head0): dims 0-3 in rows 0-3, rows 4-7 zero
        sts128(sb + KH + t * 16,
               pkh2(z[1], z[0]), pkh2(z[3], z[2]), 0u, 0u);
        // col 256+t (head1): rows 0-3 zero, dims 4-7 in rows 4-7
        sts128(sb + KH + (256 + t) * 16,
               0u, 0u, pkh2(z[5], z[4]), pkh2(z[7], z[6]));
    } else if (tid < 512) {                 // V for token t -> W cols
        const int t = tid - 256;
        const float4* xt = (const float4*)(x + (size_t)(b * SSEQ + t) * EGS);
        float4 x0 = xt[0], x1 = xt[1];
        float a[8], z[8];
        a[0] = x0.x + __ldg(Wv + 0); a[1] = x0.y + __ldg(Wv + 1);
        a[2] = x0.z + __ldg(Wv + 2); a[3] = x0.w + __ldg(Wv + 3);
        a[4] = x1.x + __ldg(Wv + 4); a[5] = x1.y + __ldg(Wv + 5);
        a[6] = x1.z + __ldg(Wv + 6); a[7] = x1.w + __ldg(Wv + 7);
        vqc8(a, z);
        // W[c][k], c=0..7: on h0-rows (k=t): {z0..z3, 1, 0,0,0}
        //                  on h1-rows (k=256+t): {z4..z7, 1, 0,0,0}
#pragma unroll
        for (int c = 0; c < 8; c++) {
            float v0 = (c < 4) ? z[c]     : (c == 4 ? 1.f : 0.f);
            float v1 = (c < 4) ? z[4 + c] : (c == 4 ? 1.f : 0.f);
            __half h0 = __float2half_rn(v0);
            __half h1 = __float2half_rn(v1);
            sts16(sb + WD + (c * 520 + t) * 2,       __half_as_ushort(h0));
            sts16(sb + WD + (c * 520 + 256 + t) * 2, __half_as_ushort(h1));
        }
    } else if (tid < 640) {                 // Q for query i (QSCALE folded)
        const int i = tid - 512;
        const float4* xt = (const float4*)(x + (size_t)(b * SSEQ + qh * QH + i) * EGS);
        float4 x0 = xt[0], x1 = xt[1];
        float a[8], z[8];
        a[0] = x0.x + __ldg(Wq + 0); a[1] = x0.y + __ldg(Wq + 1);
        a[2] = x0.z + __ldg(Wq + 2); a[3] = x0.w + __ldg(Wq + 3);
        a[4] = x1.x + __ldg(Wq + 4); a[5] = x1.y + __ldg(Wq + 5);
        a[6] = x1.z + __ldg(Wq + 6); a[7] = x1.w + __ldg(Wq + 7);
        vqc8(a, z);
#pragma unroll
        for (int d = 0; d < 8; d++) z[d] *= QSCALE;
        sts128(sb + QS + i * 16,
               pkh2(z[1], z[0]), pkh2(z[3], z[2]),
               pkh2(z[5], z[4]), pkh2(z[7], z[6]));
    }
    __syncthreads();

    // ---------------- GEMM phase: all 32 warps ----------------
    {
        const int mt = wid >> 2;            // m-tile (16 queries)
        const int ng = wid & 3;             // k-group (head = ng>>1)
        const int g  = lane >> 2;
        const int t  = lane & 3;

        // A-frag for GEMM1 (Q rows mt*16+g, +8; cols 2t,2t+1)
        const uint32_t a0 = lds32(sb + QS + (mt * 16 + g) * 16 + 4 * t);
        const uint32_t a1 = lds32(sb + QS + (mt * 16 + g + 8) * 16 + 4 * t);

        float c2[4] = {0.f, 0.f, 0.f, 0.f};   // ctx cols 0-3 + den (col 4)

#pragma unroll
        for (int ch = 0; ch < 8; ch++) {
            uint32_t pa[4];
#pragma unroll
            for (int sub = 0; sub < 2; sub++) {
                const int nt = ng * 16 + ch * 2 + sub;   // GEMM1 n-tile
                uint32_t b0 = lds32(sb + KH + (nt * 8 + g) * 16 + 4 * t);
                float d[4];
                mma1688(d, a0, a1, b0);
                pa[sub * 2 + 0] = pkh2(ex2f(d[1]), ex2f(d[0]));
                pa[sub * 2 + 1] = pkh2(ex2f(d[3]), ex2f(d[2]));
            }
            const int k0 = ng * 128 + ch * 16;
            uint32_t b0 = lds32(sb + WD + (g * 520 + k0 + 2 * t) * 2);
            uint32_t b1 = lds32(sb + WD + (g * 520 + k0 + 8 + 2 * t) * 2);
            mma16816(c2, pa, b0, b1);
        }

        // scatter partials: Red[ng][q][0..4] (4 ctx dims + den of this head)
        const int q0 = mt * 16 + g;
        float* rp  = redf + (ng * 128 + q0) * 6;
        float* rp8 = rp + 8 * 6;
        if (t < 2) {
            rp[2 * t]      = c2[0];
            rp[2 * t + 1]  = c2[1];
            rp8[2 * t]     = c2[2];
            rp8[2 * t + 1] = c2[3];
        } else if (t == 2) {
            rp[4]  = c2[0];     // den (col 4), rows g
            rp8[4] = c2[2];     // den, rows g+8
        }
    }
    __syncthreads();

    // ---------------- tail: one thread per query ----------------
    if (tid < QH) {
        const int q = tid;
        float v0[5], v1[5];
#pragma unroll
        for (int c = 0; c < 5; c++) {
            v0[c] = redf[q * 6 + c]         + redf[(128 + q) * 6 + c];
            v1[c] = redf[(256 + q) * 6 + c] + redf[(384 + q) * 6 + c];
        }

        const int tok = b * SSEQ + qh * QH + q;
        const float4* xt = (const float4*)(x + (size_t)tok * EGS);
        float4 x0 = xt[0], x1 = xt[1];
        float xi[8] = {x0.x, x0.y, x0.z, x0.w, x1.x, x1.y, x1.z, x1.w};

        float inv0 = __fdividef(1.f, v0[4]);
        float inv1 = __fdividef(1.f, v1[4]);
        float a[8], ao[8];
        a[0] = v0[0] * inv0 + __ldg(Wc + 0); a[1] = v0[1] * inv0 + __ldg(Wc + 1);
        a[2] = v0[2] * inv0 + __ldg(Wc + 2); a[3] = v0[3] * inv0 + __ldg(Wc + 3);
        a[4] = v1[0] * inv1 + __ldg(Wc + 4); a[5] = v1[1] * inv1 + __ldg(Wc + 5);
        a[6] = v1[2] * inv1 + __ldg(Wc + 6); a[7] = v1[3] * inv1 + __ldg(Wc + 7);
        vqc8(a, ao);

        float y[8], m = 0.f;
#pragma unroll
        for (int w = 0; w < 8; w++) { y[w] = xi[w] + ao[w]; m += y[w]; }
        m *= 0.125f;
        float var = 0.f;
#pragma unroll
        for (int w = 0; w < 8; w++) { float d = y[w] - m; var = fmaf(d, d, var); }
        var *= 0.125f;
        float r = rsqrtf(var + 1e-5f);
        float xn[8];
#pragma unroll
        for (int w = 0; w < 8; w++)
            xn[w] = fmaf((y[w] - m) * r, __ldg(g1 + w), __ldg(be1 + w));

        float hh[8];
#pragma unroll
        for (int i2 = 0; i2 < 8; i2++) {
            float s = __ldg(b1 + i2);
#pragma unroll
            for (int j = 0; j < 8; j++) s = fmaf(xn[j], __ldg(w1 + i2 * 8 + j), s);
            hh[i2] = s;
        }

        float hq[8];
#pragma unroll
        for (int w = 0; w < 8; w++) a[w] = hh[w] + __ldg(Wf + w);
        vqc8(a, hq);

        float z[8], m2 = 0.f;
#pragma unroll
        for (int i2 = 0; i2 < 8; i2++) {
            float s = __ldg(b2 + i2);
#pragma unroll
            for (int j = 0; j < 8; j++) s = fmaf(hq[j], __ldg(w2 + i2 * 8 + j), s);
            z[i2] = xn[i2] + s;
            m2 += z[i2];
        }
        m2 *= 0.125f;
        float v2 = 0.f;
#pragma unroll
        for (int i2 = 0; i2 < 8; i2++) { float d = z[i2] - m2; v2 = fmaf(d, d, v2); }
        v2 *= 0.125f;
        float r2 = rsqrtf(v2 + 1e-5f);
        float o[8];
#pragma unroll
        for (int i2 = 0; i2 < 8; i2++)
            o[i2] = fmaf((z[i2] - m2) * r2, __ldg(g2 + i2), __ldg(be2 + i2));

        float4* op = (float4*)(out + (size_t)tok * EGS);
        op[0] = make_float4(o[0], o[1], o[2], o[3]);
        op[1] = make_float4(o[4], o[5], o[6], o[7]);
    }
}

extern "C" void kernel_launch(void* const* d_in, const int* in_sizes, int n_in,
                              void* d_out, int out_size)
{
    const float* x   = (const float*)d_in[0];
    const float* Wq  = (const float*)d_in[1];
    const float* Wk  = (const float*)d_in[2];
    const float* Wv  = (const float*)d_in[3];
    const float* Wc  = (const float*)d_in[4];
    const float* Wf  = (const float*)d_in[5];
    const float* w1  = (const float*)d_in[6];
    const float* b1  = (const float*)d_in[7];
    const float* w2  = (const float*)d_in[8];
    const float* b2  = (const float*)d_in[9];
    const float* g1  = (const float*)d_in[10];
    const float* be1 = (const float*)d_in[11];
    const float* g2  = (const float*)d_in[12];
    const float* be2 = (const float*)d_in[13];
    float* out = (float*)d_out;

    const int ntok = in_sizes[0] / EGS;   // B*S
    const int nb   = ntok / SSEQ;         // B

    cudaFuncSetAttribute(fused_mma_kernel,
                         cudaFuncAttributeMaxDynamicSharedMemorySize, SMEM_REQ);
    fused_mma_kernel<<<nb * 2, 1024, SMEM_REQ>>>(x, Wq, Wk, Wv, Wc, Wf,
                                                 w1, b1, w2, b2,
                                                 g1, be1, g2, be2, out);
}

// round 16
// speedup vs baseline: 1.0036x; 1.0036x over previous
#include <cuda_runtime.h>
#include <cuda_fp16.h>
#include <math.h>
#include <stdint.h>

// ---------------------------------------------------------------------------
// ViTBlockQuantum via mma.sync (HMMA). VQC collapsed analytically.
// Grid = B x 4 query-quarters, 512 threads, 2 CTAs/SM (phase overlap).
// GEMM1: scores[64x512] = Q[64x8] x Khead[8x512]  (m16n8k8, head-masked K)
// exp on MUFU f32; P stays in registers as GEMM2 A-fragments.
// GEMM2: [ctx|den][64x8] = P x W (m16n8k16), W per-head 8 cols
// ---------------------------------------------------------------------------

#define EGS 8
#define SSEQ 256
#define QQN 64
#define QSCALE 0.72134752044448170368f   // 0.5 * log2(e)

// dynamic smem offsets (bytes)
#define QS   0        // Q fp16 [64 x 8]                    1024 B
#define KH   1024     // K fp16 head-masked [512 cols x 8]  8192 B
#define WD   9216     // W fp16 [8 ctx-cols x 520 k]        8320 B
#define RED  17536    // partial ctx f32 [4][64][6]         6144 B
#define SMEM_REQ 23680

static __device__ __forceinline__ float ex2f(float x) {
    float y; asm("ex2.approx.ftz.f32 %0, %1;" : "=f"(y) : "f"(x)); return y;
}
static __device__ __forceinline__ uint32_t pkh2(float hi, float lo) {
    uint32_t u; asm("cvt.rn.f16x2.f32 %0, %1, %2;" : "=r"(u) : "f"(hi), "f"(lo));
    return u;
}
static __device__ __forceinline__ uint32_t lds32(uint32_t a) {
    uint32_t v; asm volatile("ld.shared.b32 %0, [%1];" : "=r"(v) : "r"(a));
    return v;
}
static __device__ __forceinline__ void sts128(uint32_t a, uint32_t r0, uint32_t r1,
                                              uint32_t r2, uint32_t r3) {
    asm volatile("st.shared.v4.b32 [%0], {%1, %2, %3, %4};"
                 :: "r"(a), "r"(r0), "r"(r1), "r"(r2), "r"(r3) : "memory");
}
static __device__ __forceinline__ void sts16(uint32_t a, unsigned short v) {
    asm volatile("st.shared.u16 [%0], %1;" :: "r"(a), "h"(v) : "memory");
}

static __device__ __forceinline__ void mma1688(float* d, uint32_t a0, uint32_t a1,
                                               uint32_t b0) {
    asm volatile(
        "mma.sync.aligned.m16n8k8.row.col.f32.f16.f16.f32 "
        "{%0,%1,%2,%3}, {%4,%5}, {%6}, {%7,%8,%9,%10};"
        : "=f"(d[0]), "=f"(d[1]), "=f"(d[2]), "=f"(d[3])
        : "r"(a0), "r"(a1), "r"(b0),
          "f"(0.f), "f"(0.f), "f"(0.f), "f"(0.f));
}
static __device__ __forceinline__ void mma16816(float* d, const uint32_t* a,
                                                uint32_t b0, uint32_t b1) {
    asm volatile(
        "mma.sync.aligned.m16n8k16.row.col.f32.f16.f16.f32 "
        "{%0,%1,%2,%3}, {%4,%5,%6,%7}, {%8,%9}, {%0,%1,%2,%3};"
        : "+f"(d[0]), "+f"(d[1]), "+f"(d[2]), "+f"(d[3])
        : "r"(a[0]), "r"(a[1]), "r"(a[2]), "r"(a[3]), "r"(b0), "r"(b1));
}

static __device__ __forceinline__ void vqc8(const float a[8], float z[8]) {
    float c[8];
#pragma unroll
    for (int w = 0; w < 8; w++) c[w] = __cosf(a[w]);
    float p = c[0];
#pragma unroll
    for (int k = 1; k < 8; k++) { p *= c[k]; z[k] = p; }
    float q = c[1];
#pragma unroll
    for (int w = 2; w < 8; w++) q *= c[w];
    z[0] = q;
}

__global__ void __launch_bounds__(512, 2) fused_mma_kernel(
    const float* __restrict__ x,
    const float* __restrict__ Wq, const float* __restrict__ Wk,
    const float* __restrict__ Wv, const float* __restrict__ Wc,
    const float* __restrict__ Wf,
    const float* __restrict__ w1, const float* __restrict__ b1,
    const float* __restrict__ w2, const float* __restrict__ b2,
    const float* __restrict__ g1, const float* __restrict__ be1,
    const float* __restrict__ g2, const float* __restrict__ be2,
    float* __restrict__ out)
{
    extern __shared__ __align__(16) char dynsm[];
    const uint32_t sb = (uint32_t)__cvta_generic_to_shared(dynsm);
    float* redf = (float*)(dynsm + RED);

    const int b    = blockIdx.x >> 2;
    const int qq   = blockIdx.x & 3;
    const int tid  = threadIdx.x;
    const int wid  = tid >> 5;
    const int lane = tid & 31;
    const int qbase = b * SSEQ + qq * QQN;

    // prefetch tail/Q x for this thread's query (tid<64) — reused twice
    float4 px0 = make_float4(0.f, 0.f, 0.f, 0.f), px1 = px0;
    if (tid < QQN) {
        const float4* xt = (const float4*)(x + (size_t)(qbase + tid) * EGS);
        px0 = xt[0]; px1 = xt[1];
    }

    // ---------------- phase 1: stage Q / masked-K / W tiles (fp16) ----------
    if (tid < 256) {                        // K for token t -> 2 masked cols
        const int t = tid;
        const float4* xt = (const float4*)(x + (size_t)(b * SSEQ + t) * EGS);
        float4 x0 = xt[0], x1 = xt[1];
        float a[8], z[8];
        a[0] = x0.x + __ldg(Wk + 0); a[1] = x0.y + __ldg(Wk + 1);
        a[2] = x0.z + __ldg(Wk + 2); a[3] = x0.w + __ldg(Wk + 3);
        a[4] = x1.x + __ldg(Wk + 4); a[5] = x1.y + __ldg(Wk + 5);
        a[6] = x1.z + __ldg(Wk + 6); a[7] = x1.w + __ldg(Wk + 7);
        vqc8(a, z);
        sts128(sb + KH + t * 16,
               pkh2(z[1], z[0]), pkh2(z[3], z[2]), 0u, 0u);
        sts128(sb + KH + (256 + t) * 16,
               0u, 0u, pkh2(z[5], z[4]), pkh2(z[7], z[6]));
    } else {                                // V for token t -> W cols
        const int t = tid - 256;
        const float4* xt = (const float4*)(x + (size_t)(b * SSEQ + t) * EGS);
        float4 x0 = xt[0], x1 = xt[1];
        float a[8], z[8];
        a[0] = x0.x + __ldg(Wv + 0); a[1] = x0.y + __ldg(Wv + 1);
        a[2] = x0.z + __ldg(Wv + 2); a[3] = x0.w + __ldg(Wv + 3);
        a[4] = x1.x + __ldg(Wv + 4); a[5] = x1.y + __ldg(Wv + 5);
        a[6] = x1.z + __ldg(Wv + 6); a[7] = x1.w + __ldg(Wv + 7);
        vqc8(a, z);
#pragma unroll
        for (int c = 0; c < 8; c++) {
            float v0 = (c < 4) ? z[c]     : (c == 4 ? 1.f : 0.f);
            float v1 = (c < 4) ? z[4 + c] : (c == 4 ? 1.f : 0.f);
            __half h0 = __float2half_rn(v0);
            __half h1 = __float2half_rn(v1);
            sts16(sb + WD + (c * 520 + t) * 2,       __half_as_ushort(h0));
            sts16(sb + WD + (c * 520 + 256 + t) * 2, __half_as_ushort(h1));
        }
    }
    if (tid < QQN) {                        // Q for query tid (QSCALE folded)
        float a[8], z[8];
        a[0] = px0.x + __ldg(Wq + 0); a[1] = px0.y + __ldg(Wq + 1);
        a[2] = px0.z + __ldg(Wq + 2); a[3] = px0.w + __ldg(Wq + 3);
        a[4] = px1.x + __ldg(Wq + 4); a[5] = px1.y + __ldg(Wq + 5);
        a[6] = px1.z + __ldg(Wq + 6); a[7] = px1.w + __ldg(Wq + 7);
        vqc8(a, z);
#pragma unroll
        for (int d = 0; d < 8; d++) z[d] *= QSCALE;
        sts128(sb + QS + tid * 16,
               pkh2(z[1], z[0]), pkh2(z[3], z[2]),
               pkh2(z[5], z[4]), pkh2(z[7], z[6]));
    }
    __syncthreads();

    // ---------------- GEMM phase: 16 warps ----------------
    {
        const int mt = wid >> 2;            // m-tile (16 queries), 0..3
        const int ng = wid & 3;             // k-group (head = ng>>1)
        const int g  = lane >> 2;
        const int t  = lane & 3;

        const uint32_t a0 = lds32(sb + QS + (mt * 16 + g) * 16 + 4 * t);
        const uint32_t a1 = lds32(sb + QS + (mt * 16 + g + 8) * 16 + 4 * t);

        float c2[4] = {0.f, 0.f, 0.f, 0.f};

#pragma unroll
        for (int ch = 0; ch < 8; ch++) {
            uint32_t pa[4];
#pragma unroll
            for (int sub = 0; sub < 2; sub++) {
                const int nt = ng * 16 + ch * 2 + sub;
                uint32_t b0 = lds32(sb + KH + (nt * 8 + g) * 16 + 4 * t);
                float d[4];
                mma1688(d, a0, a1, b0);
                pa[sub * 2 + 0] = pkh2(ex2f(d[1]), ex2f(d[0]));
                pa[sub * 2 + 1] = pkh2(ex2f(d[3]), ex2f(d[2]));
            }
            const int k0 = ng * 128 + ch * 16;
            uint32_t b0 = lds32(sb + WD + (g * 520 + k0 + 2 * t) * 2);
            uint32_t b1 = lds32(sb + WD + (g * 520 + k0 + 8 + 2 * t) * 2);
            mma16816(c2, pa, b0, b1);
        }

        const int q0 = mt * 16 + g;
        float* rp  = redf + (ng * QQN + q0) * 6;
        float* rp8 = rp + 8 * 6;
        if (t < 2) {
            rp[2 * t]      = c2[0];
            rp[2 * t + 1]  = c2[1];
            rp8[2 * t]     = c2[2];
            rp8[2 * t + 1] = c2[3];
        } else if (t == 2) {
            rp[4]  = c2[0];
            rp8[4] = c2[2];
        }
    }
    __syncthreads();

    // ---------------- tail: one thread per query ----------------
    if (tid < QQN) {
        const int q = tid;
        float v0[5], v1[5];
#pragma unroll
        for (int c = 0; c < 5; c++) {
            v0[c] = redf[q * 6 + c]             + redf[(QQN + q) * 6 + c];
            v1[c] = redf[(2 * QQN + q) * 6 + c] + redf[(3 * QQN + q) * 6 + c];
        }

        const int tok = qbase + q;
        float xi[8] = {px0.x, px0.y, px0.z, px0.w, px1.x, px1.y, px1.z, px1.w};

        float inv0 = __fdividef(1.f, v0[4]);
        float inv1 = __fdividef(1.f, v1[4]);
        float a[8], ao[8];
        a[0] = v0[0] * inv0 + __ldg(Wc + 0); a[1] = v0[1] * inv0 + __ldg(Wc + 1);
        a[2] = v0[2] * inv0 + __ldg(Wc + 2); a[3] = v0[3] * inv0 + __ldg(Wc + 3);
        a[4] = v1[0] * inv1 + __ldg(Wc + 4); a[5] = v1[1] * inv1 + __ldg(Wc + 5);
        a[6] = v1[2] * inv1 + __ldg(Wc + 6); a[7] = v1[3] * inv1 + __ldg(Wc + 7);
        vqc8(a, ao);

        float y[8], m = 0.f;
#pragma unroll
        for (int w = 0; w < 8; w++) { y[w] = xi[w] + ao[w]; m += y[w]; }
        m *= 0.125f;
        float var = 0.f;
#pragma unroll
        for (int w = 0; w < 8; w++) { float d = y[w] - m; var = fmaf(d, d, var); }
        var *= 0.125f;
        float r = rsqrtf(var + 1e-5f);
        float xn[8];
#pragma unroll
        for (int w = 0; w < 8; w++)
            xn[w] = fmaf((y[w] - m) * r, __ldg(g1 + w), __ldg(be1 + w));

        float hh[8];
#pragma unroll
        for (int i2 = 0; i2 < 8; i2++) {
            float s = __ldg(b1 + i2);
#pragma unroll
            for (int j = 0; j < 8; j++) s = fmaf(xn[j], __ldg(w1 + i2 * 8 + j), s);
            hh[i2] = s;
        }

        float hq[8];
#pragma unroll
        for (int w = 0; w < 8; w++) a[w] = hh[w] + __ldg(Wf + w);
        vqc8(a, hq);

        float z[8], m2 = 0.f;
#pragma unroll
        for (int i2 = 0; i2 < 8; i2++) {
            float s = __ldg(b2 + i2);
#pragma unroll
            for (int j = 0; j < 8; j++) s = fmaf(hq[j], __ldg(w2 + i2 * 8 + j), s);
            z[i2] = xn[i2] + s;
            m2 += z[i2];
        }
        m2 *= 0.125f;
        float v2 = 0.f;
#pragma unroll
        for (int i2 = 0; i2 < 8; i2++) { float d = z[i2] - m2; v2 = fmaf(d, d, v2); }
        v2 *= 0.125f;
        float r2 = rsqrtf(v2 + 1e-5f);
        float o[8];
#pragma unroll
        for (int i2 = 0; i2 < 8; i2++)
            o[i2] = fmaf((z[i2] - m2) * r2, __ldg(g2 + i2), __ldg(be2 + i2));

        float4* op = (float4*)(out + (size_t)tok * EGS);
        op[0] = make_float4(o[0], o[1], o[2], o[3]);
        op[1] = make_float4(o[4], o[5], o[6], o[7]);
    }
}

extern "C" void kernel_launch(void* const* d_in, const int* in_sizes, int n_in,
                              void* d_out, int out_size)
{
    const float* x   = (const float*)d_in[0];
    const float* Wq  = (const float*)d_in[1];
    const float* Wk  = (const float*)d_in[2];
    const float* Wv  = (const float*)d_in[3];
    const float* Wc  = (const float*)d_in[4];
    const float* Wf  = (const float*)d_in[5];
    const float* w1  = (const float*)d_in[6];
    const float* b1  = (const float*)d_in[7];
    const float* w2  = (const float*)d_in[8];
    const float* b2  = (const float*)d_in[9];
    const float* g1  = (const float*)d_in[10];
    const float* be1 = (const float*)d_in[11];
    const float* g2  = (const float*)d_in[12];
    const float* be2 = (const float*)d_in[13];
    float* out = (float*)d_out;

    const int ntok = in_sizes[0] / EGS;   // B*S
    const int nb   = ntok / SSEQ;         // B

    cudaFuncSetAttribute(fused_mma_kernel,
                         cudaFuncAttributeMaxDynamicSharedMemorySize, SMEM_REQ);
    fused_mma_kernel<<<nb * 4, 512, SMEM_REQ>>>(x, Wq, Wk, Wv, Wc, Wf,
                                                w1, b1, w2, b2,
                                                g1, be1, g2, be2, out);
}

// round 17
// speedup vs baseline: 1.0332x; 1.0295x over previous
#include <cuda_runtime.h>
#include <cuda_fp16.h>
#include <math.h>
#include <stdint.h>

// ---------------------------------------------------------------------------
// ViTBlockQuantum via mma.sync (HMMA). VQC collapsed analytically.
// GEMM1: scores[128x512] = Q[128x8] x Khead[8x512]  (m16n8k8, head-masked K)
// exp on MUFU f32; P stays in registers as GEMM2 A-fragments.
// GEMM2: [ctx|den][128x8] = P x W (m16n8k16), W per-head 8 cols, split
//        even/odd-chunk accumulators (4-deep HMMA chain).
// Tail: 2 threads/query (8 warps), matvecs split, shfl exchanges.
// ---------------------------------------------------------------------------

#define EGS 8
#define SSEQ 256
#define QH 128
#define QSCALE 0.72134752044448170368f   // 0.5 * log2(e)

// dynamic smem offsets (bytes)
#define QS   0        // Q fp16 [128 x 8]                   2048 B
#define KH   2048     // K fp16 head-masked [512 cols x 8]  8192 B
#define WD   10240    // W fp16 [8 ctx-cols x 520 k]        8320 B
#define RED  18560    // partial ctx f32 [4][128][6]        12288 B
#define SMEM_REQ 30848

static __device__ __forceinline__ float ex2f(float x) {
    float y; asm("ex2.approx.ftz.f32 %0, %1;" : "=f"(y) : "f"(x)); return y;
}
static __device__ __forceinline__ uint32_t pkh2(float hi, float lo) {
    uint32_t u; asm("cvt.rn.f16x2.f32 %0, %1, %2;" : "=r"(u) : "f"(hi), "f"(lo));
    return u;
}
static __device__ __forceinline__ uint32_t lds32(uint32_t a) {
    uint32_t v; asm volatile("ld.shared.b32 %0, [%1];" : "=r"(v) : "r"(a));
    return v;
}
static __device__ __forceinline__ void sts128(uint32_t a, uint32_t r0, uint32_t r1,
                                              uint32_t r2, uint32_t r3) {
    asm volatile("st.shared.v4.b32 [%0], {%1, %2, %3, %4};"
                 :: "r"(a), "r"(r0), "r"(r1), "r"(r2), "r"(r3) : "memory");
}
static __device__ __forceinline__ void sts16(uint32_t a, unsigned short v) {
    asm volatile("st.shared.u16 [%0], %1;" :: "r"(a), "h"(v) : "memory");
}

static __device__ __forceinline__ void mma1688(float* d, uint32_t a0, uint32_t a1,
                                               uint32_t b0) {
    asm volatile(
        "mma.sync.aligned.m16n8k8.row.col.f32.f16.f16.f32 "
        "{%0,%1,%2,%3}, {%4,%5}, {%6}, {%7,%8,%9,%10};"
        : "=f"(d[0]), "=f"(d[1]), "=f"(d[2]), "=f"(d[3])
        : "r"(a0), "r"(a1), "r"(b0),
          "f"(0.f), "f"(0.f), "f"(0.f), "f"(0.f));
}
static __device__ __forceinline__ void mma16816(float* d, const uint32_t* a,
                                                uint32_t b0, uint32_t b1) {
    asm volatile(
        "mma.sync.aligned.m16n8k16.row.col.f32.f16.f16.f32 "
        "{%0,%1,%2,%3}, {%4,%5,%6,%7}, {%8,%9}, {%0,%1,%2,%3};"
        : "+f"(d[0]), "+f"(d[1]), "+f"(d[2]), "+f"(d[3])
        : "r"(a[0]), "r"(a[1]), "r"(a[2]), "r"(a[3]), "r"(b0), "r"(b1));
}

static __device__ __forceinline__ void vqc8(const float a[8], float z[8]) {
    float c[8];
#pragma unroll
    for (int w = 0; w < 8; w++) c[w] = __cosf(a[w]);
    float p = c[0];
#pragma unroll
    for (int k = 1; k < 8; k++) { p *= c[k]; z[k] = p; }
    float q = c[1];
#pragma unroll
    for (int w = 2; w < 8; w++) q *= c[w];
    z[0] = q;
}

__global__ void __launch_bounds__(1024, 1) fused_mma_kernel(
    const float* __restrict__ x,
    const float* __restrict__ Wq, const float* __restrict__ Wk,
    const float* __restrict__ Wv, const float* __restrict__ Wc,
    const float* __restrict__ Wf,
    const float* __restrict__ w1, const float* __restrict__ b1,
    const float* __restrict__ w2, const float* __restrict__ b2,
    const float* __restrict__ g1, const float* __restrict__ be1,
    const float* __restrict__ g2, const float* __restrict__ be2,
    float* __restrict__ out)
{
    extern __shared__ __align__(16) char dynsm[];
    const uint32_t sb = (uint32_t)__cvta_generic_to_shared(dynsm);
    float* redf = (float*)(dynsm + RED);

    const int b    = blockIdx.x >> 1;
    const int qh   = blockIdx.x & 1;
    const int tid  = threadIdx.x;
    const int wid  = tid >> 5;
    const int lane = tid & 31;

    // ---------------- phase 1: stage Q / masked-K / W tiles (fp16) ----------
    if (tid < 256) {                        // K for token t -> 2 masked cols
        const int t = tid;
        const float4* xt = (const float4*)(x + (size_t)(b * SSEQ + t) * EGS);
        float4 x0 = xt[0], x1 = xt[1];
        float a[8], z[8];
        a[0] = x0.x + __ldg(Wk + 0); a[1] = x0.y + __ldg(Wk + 1);
        a[2] = x0.z + __ldg(Wk + 2); a[3] = x0.w + __ldg(Wk + 3);
        a[4] = x1.x + __ldg(Wk + 4); a[5] = x1.y + __ldg(Wk + 5);
        a[6] = x1.z + __ldg(Wk + 6); a[7] = x1.w + __ldg(Wk + 7);
        vqc8(a, z);
        sts128(sb + KH + t * 16,
               pkh2(z[1], z[0]), pkh2(z[3], z[2]), 0u, 0u);
        sts128(sb + KH + (256 + t) * 16,
               0u, 0u, pkh2(z[5], z[4]), pkh2(z[7], z[6]));
    } else if (tid < 512) {                 // V for token t -> W cols
        const int t = tid - 256;
        const float4* xt = (const float4*)(x + (size_t)(b * SSEQ + t) * EGS);
        float4 x0 = xt[0], x1 = xt[1];
        float a[8], z[8];
        a[0] = x0.x + __ldg(Wv + 0); a[1] = x0.y + __ldg(Wv + 1);
        a[2] = x0.z + __ldg(Wv + 2); a[3] = x0.w + __ldg(Wv + 3);
        a[4] = x1.x + __ldg(Wv + 4); a[5] = x1.y + __ldg(Wv + 5);
        a[6] = x1.z + __ldg(Wv + 6); a[7] = x1.w + __ldg(Wv + 7);
        vqc8(a, z);
#pragma unroll
        for (int c = 0; c < 8; c++) {
            float v0 = (c < 4) ? z[c]     : (c == 4 ? 1.f : 0.f);
            float v1 = (c < 4) ? z[4 + c] : (c == 4 ? 1.f : 0.f);
            __half h0 = __float2half_rn(v0);
            __half h1 = __float2half_rn(v1);
            sts16(sb + WD + (c * 520 + t) * 2,       __half_as_ushort(h0));
            sts16(sb + WD + (c * 520 + 256 + t) * 2, __half_as_ushort(h1));
        }
    } else if (tid < 640) {                 // Q for query i (QSCALE folded)
        const int i = tid - 512;
        const float4* xt = (const float4*)(x + (size_t)(b * SSEQ + qh * QH + i) * EGS);
        float4 x0 = xt[0], x1 = xt[1];
        float a[8], z[8];
        a[0] = x0.x + __ldg(Wq + 0); a[1] = x0.y + __ldg(Wq + 1);
        a[2] = x0.z + __ldg(Wq + 2); a[3] = x0.w + __ldg(Wq + 3);
        a[4] = x1.x + __ldg(Wq + 4); a[5] = x1.y + __ldg(Wq + 5);
        a[6] = x1.z + __ldg(Wq + 6); a[7] = x1.w + __ldg(Wq + 7);
        vqc8(a, z);
#pragma unroll
        for (int d = 0; d < 8; d++) z[d] *= QSCALE;
        sts128(sb + QS + i * 16,
               pkh2(z[1], z[0]), pkh2(z[3], z[2]),
               pkh2(z[5], z[4]), pkh2(z[7], z[6]));
    }
    __syncthreads();

    // ---------------- GEMM phase: all 32 warps ----------------
    {
        const int mt = wid >> 2;            // m-tile (16 queries)
        const int ng = wid & 3;             // k-group (head = ng>>1)
        const int g  = lane >> 2;
        const int t  = lane & 3;

        const uint32_t a0 = lds32(sb + QS + (mt * 16 + g) * 16 + 4 * t);
        const uint32_t a1 = lds32(sb + QS + (mt * 16 + g + 8) * 16 + 4 * t);

        float c2x[4] = {0.f, 0.f, 0.f, 0.f};
        float c2y[4] = {0.f, 0.f, 0.f, 0.f};

#pragma unroll
        for (int ch = 0; ch < 8; ch++) {
            uint32_t pa[4];
#pragma unroll
            for (int sub = 0; sub < 2; sub++) {
                const int nt = ng * 16 + ch * 2 + sub;
                uint32_t b0 = lds32(sb + KH + (nt * 8 + g) * 16 + 4 * t);
                float d[4];
                mma1688(d, a0, a1, b0);
                pa[sub * 2 + 0] = pkh2(ex2f(d[1]), ex2f(d[0]));
                pa[sub * 2 + 1] = pkh2(ex2f(d[3]), ex2f(d[2]));
            }
            const int k0 = ng * 128 + ch * 16;
            uint32_t b0 = lds32(sb + WD + (g * 520 + k0 + 2 * t) * 2);
            uint32_t b1 = lds32(sb + WD + (g * 520 + k0 + 8 + 2 * t) * 2);
            mma16816((ch & 1) ? c2y : c2x, pa, b0, b1);
        }
        float c2[4];
#pragma unroll
        for (int j = 0; j < 4; j++) c2[j] = c2x[j] + c2y[j];

        const int q0 = mt * 16 + g;
        float* rp  = redf + (ng * 128 + q0) * 6;
        float* rp8 = rp + 8 * 6;
        if (t < 2) {
            rp[2 * t]      = c2[0];
            rp[2 * t + 1]  = c2[1];
            rp8[2 * t]     = c2[2];
            rp8[2 * t + 1] = c2[3];
        } else if (t == 2) {
            rp[4]  = c2[0];
            rp8[4] = c2[2];
        }
    }
    __syncthreads();

    // ---------------- tail: 2 threads per query (8 warps) ----------------
    if (tid < 256) {
        const int q = tid >> 1;
        const int s = tid & 1;              // head / row-half owner

        // this head's partials (2 k-groups)
        float v[5];
#pragma unroll
        for (int c = 0; c < 5; c++)
            v[c] = redf[((2 * s) * 128 + q) * 6 + c]
                 + redf[((2 * s + 1) * 128 + q) * 6 + c];

        float inv = __fdividef(1.f, v[4]);
        float ah[4];
#pragma unroll
        for (int j = 0; j < 4; j++)
            ah[j] = v[j] * inv + __ldg(Wc + 4 * s + j);

        // exchange halves -> full a[8]
        float a[8];
#pragma unroll
        for (int j = 0; j < 4; j++) {
            a[4 * s + j] = ah[j];
            a[4 * (1 - s) + j] = __shfl_xor_sync(0xffffffffu, ah[j], 1);
        }
        float ao[8];
        vqc8(a, ao);

        const int tok = b * SSEQ + qh * QH + q;
        const float4* xt = (const float4*)(x + (size_t)tok * EGS);
        float4 x0 = xt[0], x1 = xt[1];
        float xi[8] = {x0.x, x0.y, x0.z, x0.w, x1.x, x1.y, x1.z, x1.w};

        float y[8], m = 0.f;
#pragma unroll
        for (int w = 0; w < 8; w++) { y[w] = xi[w] + ao[w]; m += y[w]; }
        m *= 0.125f;
        float var = 0.f;
#pragma unroll
        for (int w = 0; w < 8; w++) { float d = y[w] - m; var = fmaf(d, d, var); }
        var *= 0.125f;
        float r = rsqrtf(var + 1e-5f);
        float xn[8];
#pragma unroll
        for (int w = 0; w < 8; w++)
            xn[w] = fmaf((y[w] - m) * r, __ldg(g1 + w), __ldg(be1 + w));

        // matvec1: rows 4s..4s+3 only
        float hh4[4];
#pragma unroll
        for (int i2 = 0; i2 < 4; i2++) {
            const int row = 4 * s + i2;
            float sum = __ldg(b1 + row);
#pragma unroll
            for (int j = 0; j < 8; j++)
                sum = fmaf(xn[j], __ldg(w1 + row * 8 + j), sum);
            hh4[i2] = sum;
        }
        // exchange -> full h
        float h8[8];
#pragma unroll
        for (int j = 0; j < 4; j++) {
            h8[4 * s + j] = hh4[j];
            h8[4 * (1 - s) + j] = __shfl_xor_sync(0xffffffffu, hh4[j], 1);
        }

        float hq[8];
#pragma unroll
        for (int w = 0; w < 8; w++) a[w] = h8[w] + __ldg(Wf + w);
        vqc8(a, hq);

        // matvec2: rows 4s..4s+3; z rows + LN2 via shfl reduction
        float z4[4], zsum = 0.f;
#pragma unroll
        for (int i2 = 0; i2 < 4; i2++) {
            const int row = 4 * s + i2;
            float sum = __ldg(b2 + row);
#pragma unroll
            for (int j = 0; j < 8; j++)
                sum = fmaf(hq[j], __ldg(w2 + row * 8 + j), sum);
            z4[i2] = xn[row] + sum;
            zsum += z4[i2];
        }
        zsum += __shfl_xor_sync(0xffffffffu, zsum, 1);
        float m2 = zsum * 0.125f;
        float vp = 0.f;
#pragma unroll
        for (int i2 = 0; i2 < 4; i2++) { float d = z4[i2] - m2; vp = fmaf(d, d, vp); }
        vp += __shfl_xor_sync(0xffffffffu, vp, 1);
        float r2 = rsqrtf(vp * 0.125f + 1e-5f);

        float o0 = fmaf((z4[0] - m2) * r2, __ldg(g2 + 4 * s + 0), __ldg(be2 + 4 * s + 0));
        float o1 = fmaf((z4[1] - m2) * r2, __ldg(g2 + 4 * s + 1), __ldg(be2 + 4 * s + 1));
        float o2 = fmaf((z4[2] - m2) * r2, __ldg(g2 + 4 * s + 2), __ldg(be2 + 4 * s + 2));
        float o3 = fmaf((z4[3] - m2) * r2, __ldg(g2 + 4 * s + 3), __ldg(be2 + 4 * s + 3));

        float4* op = (float4*)(out + (size_t)tok * EGS + 4 * s);
        *op = make_float4(o0, o1, o2, o3);
    }
}

extern "C" void kernel_launch(void* const* d_in, const int* in_sizes, int n_in,
                              void* d_out, int out_size)
{
    const float* x   = (const float*)d_in[0];
    const float* Wq  = (const float*)d_in[1];
    const float* Wk  = (const float*)d_in[2];
    const float* Wv  = (const float*)d_in[3];
    const float* Wc  = (const float*)d_in[4];
    const float* Wf  = (const float*)d_in[5];
    const float* w1  = (const float*)d_in[6];
    const float* b1  = (const float*)d_in[7];
    const float* w2  = (const float*)d_in[8];
    const float* b2  = (const float*)d_in[9];
    const float* g1  = (const float*)d_in[10];
    const float* be1 = (const float*)d_in[11];
    const float* g2  = (const float*)d_in[12];
    const float* be2 = (const float*)d_in[13];
    float* out = (float*)d_out;

    const int ntok = in_sizes[0] / EGS;   // B*S
    const int nb   = ntok / SSEQ;         // B

    cudaFuncSetAttribute(fused_mma_kernel,
                         cudaFuncAttributeMaxDynamicSharedMemorySize, SMEM_REQ);
    fused_mma_kernel<<<nb * 2, 1024, SMEM_REQ>>>(x, Wq, Wk, Wv, Wc, Wf,
                                                 w1, b1, w2, b2,
                                                 g1, be1, g2, be2, out);
}